// round 6
// baseline (speedup 1.0000x reference)
#include <cuda_runtime.h>
#include <math.h>

#define B_SZ   1024
#define HID    384
#define MH     300
#define OPAD   320   // padded row stride; cols 300..319 stay zero (zero-init globals)

typedef unsigned long long u64;

// Scratch (device globals; allocations forbidden). Zero-initialized at load;
// padding columns are never written, so they remain exactly 0.0f.
__device__ float g_s1[B_SZ * HID];
__device__ float g_s2[B_SZ * HID];
__device__ float g_Axb[B_SZ * OPAD];
__device__ float g_By [B_SZ * OPAD];
__device__ float g_klpart[B_SZ];
__device__ float g_T0[B_SZ];
__device__ float g_rowpartT[B_SZ * 32];   // [i][jt]  (transposed, coalesced reads)

__device__ __forceinline__ float softplusf(float x) {
    return fmaxf(x, 0.f) + log1pf(expf(-fabsf(x)));
}

// Packed f32x2 ops on u64-resident data
__device__ __forceinline__ u64 f2add_u(u64 a, u64 b) {
    u64 d; asm("add.rn.f32x2 %0, %1, %2;" : "=l"(d) : "l"(a), "l"(b)); return d;
}
__device__ __forceinline__ u64 f2fma_u(u64 a, u64 b, u64 c) {
    u64 d; asm("fma.rn.f32x2 %0, %1, %2, %3;" : "=l"(d) : "l"(a), "l"(b), "l"(c)); return d;
}
__device__ __forceinline__ u64 f2relu_u(u64 a) {
    float lo, hi;
    asm("mov.b64 {%0,%1}, %2;" : "=f"(lo), "=f"(hi) : "l"(a));
    lo = fmaxf(lo, 0.f);
    hi = fmaxf(hi, 0.f);
    u64 d;
    asm("mov.b64 %0, {%1,%2};" : "=l"(d) : "f"(lo), "f"(hi));
    return d;
}
__device__ __forceinline__ float f2hsum(u64 a) {
    float lo, hi;
    asm("mov.b64 {%0,%1}, %2;" : "=f"(lo), "=f"(hi) : "l"(a));
    return lo + hi;
}
__device__ __forceinline__ u64 fpack(float x, float y) {
    u64 d; asm("mov.b64 %0, {%1,%2};" : "=l"(d) : "f"(x), "f"(y)); return d;
}

// ---------------------------------------------------------------------------
// K1: per-batch-row fused  einsum -> (mu,sig) -> sample -> KL partial
// grid 1024, block 192. HBM-bound (176 MB).
// ---------------------------------------------------------------------------
__global__ __launch_bounds__(192) void k1_fuse(
    const float* __restrict__ zl, const float* __restrict__ zv,
    const float* __restrict__ wl_g, const float* __restrict__ bl_g,
    const float* __restrict__ wv_g, const float* __restrict__ bv_g,
    const float* __restrict__ eps1, const float* __restrict__ eps2)
{
    __shared__ float z1s[768], z2s[768];
    __shared__ float wls[20], wvs[36];
    __shared__ float redw[6];
    const int b = blockIdx.x, t = threadIdx.x;
    if (t < 20) wls[t] = wl_g[t];
    if (t >= 32 && t < 68) wvs[t - 32] = wv_g[t - 32];
    __syncthreads();
    const float bl = bl_g[0], bv = bv_g[0];
    {
        const float4* p = (const float4*)(zl + (size_t)b * 20 * 768) + t;
        float4 a = make_float4(bl, bl, bl, bl);
        #pragma unroll
        for (int s = 0; s < 20; ++s) {
            float4 v = p[s * 192];
            float w = wls[s];
            a.x = fmaf(v.x, w, a.x); a.y = fmaf(v.y, w, a.y);
            a.z = fmaf(v.z, w, a.z); a.w = fmaf(v.w, w, a.w);
        }
        ((float4*)z1s)[t] = a;
    }
    {
        const float4* p = (const float4*)(zv + (size_t)b * 36 * 768) + t;
        float4 a = make_float4(bv, bv, bv, bv);
        #pragma unroll
        for (int s = 0; s < 36; ++s) {
            float4 v = p[s * 192];
            float w = wvs[s];
            a.x = fmaf(v.x, w, a.x); a.y = fmaf(v.y, w, a.y);
            a.z = fmaf(v.z, w, a.z); a.w = fmaf(v.w, w, a.w);
        }
        ((float4*)z2s)[t] = a;
    }
    __syncthreads();
    float klacc = 0.f;
    #pragma unroll
    for (int q = 0; q < 2; ++q) {
        int k = t + q * 192;
        float mu1 = z1s[k], mu2 = z2s[k];
        float sg1 = softplusf(z1s[k + HID]) + 1e-7f;
        float sg2 = softplusf(z2s[k + HID]) + 1e-7f;
        float e1 = eps1[b * HID + k], e2 = eps2[b * HID + k];
        float s1v = fmaf(sg1, e1, mu1);
        float s2v = fmaf(sg2, e2, mu2);
        g_s1[b * HID + k] = s1v;
        g_s2[b * HID + k] = s2v;
        float d1 = (s1v - mu2) / sg2;
        float d2 = (s2v - mu1) / sg1;
        klacc += 0.5f * (d1 * d1 + d2 * d2 - e1 * e1 - e2 * e2);
    }
    #pragma unroll
    for (int off = 16; off > 0; off >>= 1)
        klacc += __shfl_xor_sync(0xFFFFFFFFu, klacc, off);
    if ((t & 31) == 0) redw[t >> 5] = klacc;
    __syncthreads();
    if (t == 0)
        g_klpart[b] = redw[0] + redw[1] + redw[2] + redw[3] + redw[4] + redw[5];
}

// ---------------------------------------------------------------------------
// K2: Axb = s1 @ W1x^T + b1 ;  By = s2 @ W1y^T
// grid (16,5,2), block 256.  Tile 64x64, u64-packed over k, 4x4/thread.
// ---------------------------------------------------------------------------
__global__ __launch_bounds__(256) void k2_gemm(
    const float* __restrict__ W1, const float* __restrict__ b1)
{
    __shared__ u64 As[64][17];
    __shared__ u64 Ws[64][17];

    const int z  = blockIdx.z;
    const int r0 = blockIdx.x * 64;
    const int c0 = blockIdx.y * 64;
    const float* S = z ? g_s2 : g_s1;
    float*       O = z ? g_By : g_Axb;
    const int koff = z ? HID : 0;

    const int t  = threadIdx.x;
    const int tj = t & 15;
    const int ti = t >> 4;

    u64 acc[4][4];
    #pragma unroll
    for (int r = 0; r < 4; ++r)
        #pragma unroll
        for (int c = 0; c < 4; ++c) acc[r][c] = 0ull;

    for (int kk2 = 0; kk2 < 192; kk2 += 16) {
        __syncthreads();
        #pragma unroll
        for (int i = 0; i < 4; ++i) {
            int e = t + i * 256;
            int row = e >> 4, k2 = e & 15;
            As[row][k2] = *(const u64*)&S[(r0 + row) * HID + (kk2 + k2) * 2];
            int col = c0 + row;
            Ws[row][k2] = (col < MH)
                ? *(const u64*)&W1[col * 768 + koff + (kk2 + k2) * 2] : 0ull;
        }
        __syncthreads();
        #pragma unroll 4
        for (int k2 = 0; k2 < 16; ++k2) {
            u64 a[4], w[4];
            #pragma unroll
            for (int r = 0; r < 4; ++r) a[r] = As[ti + 16 * r][k2];
            #pragma unroll
            for (int c = 0; c < 4; ++c) w[c] = Ws[tj + 16 * c][k2];
            #pragma unroll
            for (int r = 0; r < 4; ++r)
                #pragma unroll
                for (int c = 0; c < 4; ++c)
                    acc[r][c] = f2fma_u(a[r], w[c], acc[r][c]);
        }
    }
    #pragma unroll
    for (int r = 0; r < 4; ++r) {
        int row = r0 + ti + 16 * r;
        #pragma unroll
        for (int c = 0; c < 4; ++c) {
            int col = c0 + tj + 16 * c;
            if (col < MH) {
                float v = f2hsum(acc[r][c]);
                if (z == 0) v += b1[col];
                O[row * OPAD + col] = v;
            }
        }
    }
}

// ---------------------------------------------------------------------------
// K3: pairwise grid.  u[i][j] = sum_k relu(Axb[j,k] + By[i,k]) * w2[k]
// Tile 64(i) x 32(j), block 128, grid (32 jt, 16 it) = 512 CTAs.
// 4x4 pairs/thread, u64-packed over k, register-prefetch pipeline.
// Diagonal pairs also produce T0[i] = softplus(u[i][i] + b2).
// ---------------------------------------------------------------------------
__global__ __launch_bounds__(128) void k3_pair(
    const float* __restrict__ W2, const float* __restrict__ b2g)
{
    __shared__ u64 Bys[64][17];   // i-tile rows
    __shared__ u64 Axs[32][17];   // j-tile rows
    __shared__ u64 w2s[160];
    __shared__ float rowred[64][9];

    const int jt = blockIdx.x;           // 0..31
    const int it = blockIdx.y;           // 0..15
    const int i0 = it * 64, j0 = jt * 32;
    const int t  = threadIdx.x;          // 0..127
    const int tj = t & 7;                // j sub (x4, stride 8)
    const int ti = t >> 3;               // i sub (x4, stride 16)

    for (int kk = t; kk < 160; kk += 128) {
        int k = 2 * kk;
        float2 w = make_float2(k < MH ? W2[k] : 0.f,
                               k + 1 < MH ? W2[k + 1] : 0.f);
        w2s[kk] = *(const u64*)&w;
    }

    // float4 prefetch mapping: 768 units/chunk (512 Bys + 256 Axs), 6/thread
    const float* src[6];
    int   srow[6], sf4[6];
    #pragma unroll
    for (int i = 0; i < 6; ++i) {
        int u = t + i * 128;
        if (u < 512) { srow[i] = u >> 3; sf4[i] = u & 7;
                       src[i] = &g_By[(i0 + srow[i]) * OPAD + sf4[i] * 4]; }
        else { int v = u - 512; srow[i] = v >> 3; sf4[i] = v & 7;
               src[i] = &g_Axb[(j0 + srow[i]) * OPAD + sf4[i] * 4]; }
    }

    u64 acc[4][4];
    #pragma unroll
    for (int r = 0; r < 4; ++r)
        #pragma unroll
        for (int c = 0; c < 4; ++c) acc[r][c] = 0ull;

    float4 pf[6];
    #pragma unroll
    for (int i = 0; i < 6; ++i) pf[i] = *(const float4*)src[i];

    for (int c = 0; c < 10; ++c) {
        __syncthreads();
        #pragma unroll
        for (int i = 0; i < 6; ++i) {
            int u = t + i * 128;
            if (u < 512) {
                Bys[srow[i]][2 * sf4[i]]     = fpack(pf[i].x, pf[i].y);
                Bys[srow[i]][2 * sf4[i] + 1] = fpack(pf[i].z, pf[i].w);
            } else {
                Axs[srow[i]][2 * sf4[i]]     = fpack(pf[i].x, pf[i].y);
                Axs[srow[i]][2 * sf4[i] + 1] = fpack(pf[i].z, pf[i].w);
            }
        }
        __syncthreads();
        if (c < 9) {
            int off = (c + 1) * 32;
            #pragma unroll
            for (int i = 0; i < 6; ++i) pf[i] = *(const float4*)(src[i] + off);
        }
        #pragma unroll 4
        for (int k2 = 0; k2 < 16; ++k2) {
            u64 wp = w2s[c * 16 + k2];
            u64 a[4], b[4];
            #pragma unroll
            for (int cc = 0; cc < 4; ++cc) a[cc] = Axs[tj + 8 * cc][k2];
            #pragma unroll
            for (int r = 0; r < 4; ++r) b[r] = Bys[ti + 16 * r][k2];
            #pragma unroll
            for (int r = 0; r < 4; ++r)
                #pragma unroll
                for (int cc = 0; cc < 4; ++cc)
                    acc[r][cc] = f2fma_u(f2relu_u(f2add_u(a[cc], b[r])), wp,
                                         acc[r][cc]);
        }
    }

    const float b2v = b2g[0];

    // Diagonal: global i == global j  ->  T0
    const int d = j0 - i0;   // diagonal hits this block iff d in {0,32}
    if (d == 0 || d == 32) {
        #pragma unroll
        for (int r = 0; r < 4; ++r)
            #pragma unroll
            for (int cc = 0; cc < 4; ++cc) {
                int iloc = ti + 16 * r, jloc = tj + 8 * cc;
                if (iloc == jloc + d)
                    g_T0[i0 + iloc] = softplusf(f2hsum(acc[r][cc]) + b2v);
            }
    }

    __syncthreads();
    #pragma unroll
    for (int r = 0; r < 4; ++r) {
        float e = 0.f;
        #pragma unroll
        for (int cc = 0; cc < 4; ++cc)
            e += expf(f2hsum(acc[r][cc]) + b2v);
        rowred[ti + 16 * r][tj] = e;
    }
    __syncthreads();
    if (t < 64) {
        float s = 0.f;
        #pragma unroll
        for (int cc = 0; cc < 8; ++cc) s += rowred[t][cc];
        g_rowpartT[(i0 + t) * 32 + jt] = s;
    }
}

// ---------------------------------------------------------------------------
// K5: final reduction.  1024 threads, one row each; coalesced float4 reads.
// ---------------------------------------------------------------------------
__global__ __launch_bounds__(1024) void k5_final(float* __restrict__ out)
{
    __shared__ double skl[32], st0[32], sL[32];
    const int t = threadIdx.x;
    float rs = 0.f;
    const float4* rp = (const float4*)&g_rowpartT[t * 32];
    #pragma unroll
    for (int q = 0; q < 8; ++q) {
        float4 v = rp[q];
        rs += (v.x + v.y) + (v.z + v.w);
    }
    // logsumexp_j softplus(u) = log(B + sum_j e^u)
    double kl = (double)g_klpart[t];
    double t0 = (double)g_T0[t];
    double L  = (double)logf((float)B_SZ + rs);
    #pragma unroll
    for (int off = 16; off > 0; off >>= 1) {
        kl += __shfl_xor_sync(0xFFFFFFFFu, kl, off);
        t0 += __shfl_xor_sync(0xFFFFFFFFu, t0, off);
        L  += __shfl_xor_sync(0xFFFFFFFFu, L,  off);
    }
    if ((t & 31) == 0) { skl[t >> 5] = kl; st0[t >> 5] = t0; sL[t >> 5] = L; }
    __syncthreads();
    if (t < 32) {
        kl = skl[t]; t0 = st0[t]; L = sL[t];
        #pragma unroll
        for (int off = 16; off > 0; off >>= 1) {
            kl += __shfl_xor_sync(0xFFFFFFFFu, kl, off);
            t0 += __shfl_xor_sync(0xFFFFFFFFu, t0, off);
            L  += __shfl_xor_sync(0xFFFFFFFFu, L,  off);
        }
        if (t == 0) {
            double d_skl = kl / (double)B_SZ * 0.5;
            double t0m   = t0 / (double)B_SZ;
            double meanL = L  / (double)B_SZ;
            double lower = t0m - (meanL - log((double)B_SZ));
            out[0] = (float)(d_skl - lower);
        }
    }
}

// ---------------------------------------------------------------------------
extern "C" void kernel_launch(void* const* d_in, const int* in_sizes, int n_in,
                              void* d_out, int out_size)
{
    const float* zl    = (const float*)d_in[0];
    const float* zv    = (const float*)d_in[1];
    const float* fclw  = (const float*)d_in[2];
    const float* fclb  = (const float*)d_in[3];
    const float* fcvw  = (const float*)d_in[4];
    const float* fcvb  = (const float*)d_in[5];
    const float* W1    = (const float*)d_in[6];
    const float* b1    = (const float*)d_in[7];
    const float* W2    = (const float*)d_in[8];
    const float* b2    = (const float*)d_in[9];
    const float* eps1  = (const float*)d_in[10];
    const float* eps2  = (const float*)d_in[11];
    float* out = (float*)d_out;

    k1_fuse<<<B_SZ, 192>>>(zl, zv, fclw, fclb, fcvw, fcvb, eps1, eps2);
    k2_gemm<<<dim3(16, 5, 2), 256>>>(W1, b1);
    k3_pair<<<dim3(32, 16), 128>>>(W2, b2);
    k5_final<<<1, 1024>>>(out);
}

// round 7
// speedup vs baseline: 1.0328x; 1.0328x over previous
#include <cuda_runtime.h>
#include <math.h>

#define B_SZ   1024
#define HID    384
#define MH     300
#define OPAD   320   // padded row stride; cols 300..319 stay zero (zero-init globals)
#define NJT    16    // j-tiles in k3

typedef unsigned long long u64;

// Scratch (device globals; allocations forbidden). Zero-initialized at load;
// padding columns are never written, so they remain exactly 0.0f.
__device__ float g_s1[B_SZ * HID];
__device__ float g_s2[B_SZ * HID];
__device__ float g_Axb[B_SZ * OPAD];
__device__ float g_By [B_SZ * OPAD];
__device__ float g_klpart[B_SZ];
__device__ float g_T0[B_SZ];
__device__ float g_rowpartT[B_SZ * NJT];   // [i][jt], 64B rows, coalesced
__device__ unsigned g_done;                // zero-init; self-restoring

__device__ __forceinline__ float softplusf(float x) {
    return fmaxf(x, 0.f) + log1pf(expf(-fabsf(x)));
}

// Packed f32x2 ops on u64-resident data
__device__ __forceinline__ u64 f2add_u(u64 a, u64 b) {
    u64 d; asm("add.rn.f32x2 %0, %1, %2;" : "=l"(d) : "l"(a), "l"(b)); return d;
}
__device__ __forceinline__ u64 f2fma_u(u64 a, u64 b, u64 c) {
    u64 d; asm("fma.rn.f32x2 %0, %1, %2, %3;" : "=l"(d) : "l"(a), "l"(b), "l"(c)); return d;
}
__device__ __forceinline__ u64 f2relu_u(u64 a) {
    float lo, hi;
    asm("mov.b64 {%0,%1}, %2;" : "=f"(lo), "=f"(hi) : "l"(a));
    lo = fmaxf(lo, 0.f);
    hi = fmaxf(hi, 0.f);
    u64 d;
    asm("mov.b64 %0, {%1,%2};" : "=l"(d) : "f"(lo), "f"(hi));
    return d;
}
__device__ __forceinline__ float f2hsum(u64 a) {
    float lo, hi;
    asm("mov.b64 {%0,%1}, %2;" : "=f"(lo), "=f"(hi) : "l"(a));
    return lo + hi;
}
__device__ __forceinline__ u64 fpack(float x, float y) {
    u64 d; asm("mov.b64 %0, {%1,%2};" : "=l"(d) : "f"(x), "f"(y)); return d;
}

// ---------------------------------------------------------------------------
// K1: per-batch-row fused  einsum -> (mu,sig) -> sample -> KL partial
// grid 1024, block 192. HBM-bound (176 MB).
// ---------------------------------------------------------------------------
__global__ __launch_bounds__(192) void k1_fuse(
    const float* __restrict__ zl, const float* __restrict__ zv,
    const float* __restrict__ wl_g, const float* __restrict__ bl_g,
    const float* __restrict__ wv_g, const float* __restrict__ bv_g,
    const float* __restrict__ eps1, const float* __restrict__ eps2)
{
    __shared__ float z1s[768], z2s[768];
    __shared__ float wls[20], wvs[36];
    __shared__ float redw[6];
    const int b = blockIdx.x, t = threadIdx.x;
    if (t < 20) wls[t] = wl_g[t];
    if (t >= 32 && t < 68) wvs[t - 32] = wv_g[t - 32];
    __syncthreads();
    const float bl = bl_g[0], bv = bv_g[0];
    {
        const float4* p = (const float4*)(zl + (size_t)b * 20 * 768) + t;
        float4 a = make_float4(bl, bl, bl, bl);
        #pragma unroll
        for (int s = 0; s < 20; ++s) {
            float4 v = p[s * 192];
            float w = wls[s];
            a.x = fmaf(v.x, w, a.x); a.y = fmaf(v.y, w, a.y);
            a.z = fmaf(v.z, w, a.z); a.w = fmaf(v.w, w, a.w);
        }
        ((float4*)z1s)[t] = a;
    }
    {
        const float4* p = (const float4*)(zv + (size_t)b * 36 * 768) + t;
        float4 a = make_float4(bv, bv, bv, bv);
        #pragma unroll
        for (int s = 0; s < 36; ++s) {
            float4 v = p[s * 192];
            float w = wvs[s];
            a.x = fmaf(v.x, w, a.x); a.y = fmaf(v.y, w, a.y);
            a.z = fmaf(v.z, w, a.z); a.w = fmaf(v.w, w, a.w);
        }
        ((float4*)z2s)[t] = a;
    }
    __syncthreads();
    float klacc = 0.f;
    #pragma unroll
    for (int q = 0; q < 2; ++q) {
        int k = t + q * 192;
        float mu1 = z1s[k], mu2 = z2s[k];
        float sg1 = softplusf(z1s[k + HID]) + 1e-7f;
        float sg2 = softplusf(z2s[k + HID]) + 1e-7f;
        float e1 = eps1[b * HID + k], e2 = eps2[b * HID + k];
        float s1v = fmaf(sg1, e1, mu1);
        float s2v = fmaf(sg2, e2, mu2);
        g_s1[b * HID + k] = s1v;
        g_s2[b * HID + k] = s2v;
        float d1 = (s1v - mu2) / sg2;
        float d2 = (s2v - mu1) / sg1;
        klacc += 0.5f * (d1 * d1 + d2 * d2 - e1 * e1 - e2 * e2);
    }
    #pragma unroll
    for (int off = 16; off > 0; off >>= 1)
        klacc += __shfl_xor_sync(0xFFFFFFFFu, klacc, off);
    if ((t & 31) == 0) redw[t >> 5] = klacc;
    __syncthreads();
    if (t == 0)
        g_klpart[b] = redw[0] + redw[1] + redw[2] + redw[3] + redw[4] + redw[5];
}

// ---------------------------------------------------------------------------
// K2: Axb = s1 @ W1x^T + b1 ;  By = s2 @ W1y^T
// grid (16,5,2), block 256.  Tile 64x64, u64-packed over k, 4x4/thread.
// ---------------------------------------------------------------------------
__global__ __launch_bounds__(256) void k2_gemm(
    const float* __restrict__ W1, const float* __restrict__ b1)
{
    __shared__ u64 As[64][17];
    __shared__ u64 Ws[64][17];

    const int z  = blockIdx.z;
    const int r0 = blockIdx.x * 64;
    const int c0 = blockIdx.y * 64;
    const float* S = z ? g_s2 : g_s1;
    float*       O = z ? g_By : g_Axb;
    const int koff = z ? HID : 0;

    const int t  = threadIdx.x;
    const int tj = t & 15;
    const int ti = t >> 4;

    u64 acc[4][4];
    #pragma unroll
    for (int r = 0; r < 4; ++r)
        #pragma unroll
        for (int c = 0; c < 4; ++c) acc[r][c] = 0ull;

    for (int kk2 = 0; kk2 < 192; kk2 += 16) {
        __syncthreads();
        #pragma unroll
        for (int i = 0; i < 4; ++i) {
            int e = t + i * 256;
            int row = e >> 4, k2 = e & 15;
            As[row][k2] = *(const u64*)&S[(r0 + row) * HID + (kk2 + k2) * 2];
            int col = c0 + row;
            Ws[row][k2] = (col < MH)
                ? *(const u64*)&W1[col * 768 + koff + (kk2 + k2) * 2] : 0ull;
        }
        __syncthreads();
        #pragma unroll 4
        for (int k2 = 0; k2 < 16; ++k2) {
            u64 a[4], w[4];
            #pragma unroll
            for (int r = 0; r < 4; ++r) a[r] = As[ti + 16 * r][k2];
            #pragma unroll
            for (int c = 0; c < 4; ++c) w[c] = Ws[tj + 16 * c][k2];
            #pragma unroll
            for (int r = 0; r < 4; ++r)
                #pragma unroll
                for (int c = 0; c < 4; ++c)
                    acc[r][c] = f2fma_u(a[r], w[c], acc[r][c]);
        }
    }
    #pragma unroll
    for (int r = 0; r < 4; ++r) {
        int row = r0 + ti + 16 * r;
        #pragma unroll
        for (int c = 0; c < 4; ++c) {
            int col = c0 + tj + 16 * c;
            if (col < MH) {
                float v = f2hsum(acc[r][c]);
                if (z == 0) v += b1[col];
                O[row * OPAD + col] = v;
            }
        }
    }
}

// ---------------------------------------------------------------------------
// K3: pairwise grid + fused final reduction in the last-arriving block.
// u[i][j] = sum_k relu(Axb[j,k] + By[i,k]) * w2[k]
// grid (16 jt, 16 it), block 256. 64x64 tile, 4x4/thread, u64-packed,
// register-prefetch pipeline.  Diagonal blocks write T0.
// ---------------------------------------------------------------------------
__global__ __launch_bounds__(256) void k3_pair(
    const float* __restrict__ W2, const float* __restrict__ b2g,
    float* __restrict__ out)
{
    __shared__ u64 Bys[64][17];
    __shared__ u64 Axs[64][17];
    __shared__ u64 w2s[160];
    __shared__ float rowred[64][17];
    __shared__ int sLast;
    __shared__ double sred[3][8];

    const int jt = blockIdx.x;
    const int it = blockIdx.y;
    const int i0 = it * 64, j0 = jt * 64;
    const int t  = threadIdx.x;
    const int tj = t & 15;
    const int ti = t >> 4;

    if (t < 160) {
        int k = 2 * t;
        float2 w = make_float2(k < MH ? W2[k] : 0.f,
                               k + 1 < MH ? W2[k + 1] : 0.f);
        w2s[t] = *(const u64*)&w;
    }

    // float4 prefetch mapping: unit u in [0,512): row=u>>3, f4=u&7
    const int rA = t >> 3,          fA = t & 7;
    const int rB = (t + 256) >> 3,  fB = t & 7;
    const float* byA = &g_By [(i0 + rA) * OPAD + fA * 4];
    const float* byB = &g_By [(i0 + rB) * OPAD + fB * 4];
    const float* axA = &g_Axb[(j0 + rA) * OPAD + fA * 4];
    const float* axB = &g_Axb[(j0 + rB) * OPAD + fB * 4];

    u64 acc[4][4];
    #pragma unroll
    for (int r = 0; r < 4; ++r)
        #pragma unroll
        for (int c = 0; c < 4; ++c) acc[r][c] = 0ull;

    float4 pb0 = *(const float4*)(byA);
    float4 pb1 = *(const float4*)(byB);
    float4 pa0 = *(const float4*)(axA);
    float4 pa1 = *(const float4*)(axB);

    for (int c = 0; c < 10; ++c) {
        __syncthreads();
        Bys[rA][2 * fA]     = fpack(pb0.x, pb0.y);
        Bys[rA][2 * fA + 1] = fpack(pb0.z, pb0.w);
        Bys[rB][2 * fB]     = fpack(pb1.x, pb1.y);
        Bys[rB][2 * fB + 1] = fpack(pb1.z, pb1.w);
        Axs[rA][2 * fA]     = fpack(pa0.x, pa0.y);
        Axs[rA][2 * fA + 1] = fpack(pa0.z, pa0.w);
        Axs[rB][2 * fB]     = fpack(pa1.x, pa1.y);
        Axs[rB][2 * fB + 1] = fpack(pa1.z, pa1.w);
        __syncthreads();
        if (c < 9) {
            int off = (c + 1) * 32;
            pb0 = *(const float4*)(byA + off);
            pb1 = *(const float4*)(byB + off);
            pa0 = *(const float4*)(axA + off);
            pa1 = *(const float4*)(axB + off);
        }
        #pragma unroll 4
        for (int k2 = 0; k2 < 16; ++k2) {
            u64 wp = w2s[c * 16 + k2];
            u64 a[4], b[4];
            #pragma unroll
            for (int cc = 0; cc < 4; ++cc) a[cc] = Axs[tj + 16 * cc][k2];
            #pragma unroll
            for (int r = 0; r < 4; ++r) b[r] = Bys[ti + 16 * r][k2];
            #pragma unroll
            for (int r = 0; r < 4; ++r)
                #pragma unroll
                for (int cc = 0; cc < 4; ++cc)
                    acc[r][cc] = f2fma_u(f2relu_u(f2add_u(a[cc], b[r])), wp,
                                         acc[r][cc]);
        }
    }

    const float b2v = b2g[0];

    // Diagonal blocks: T0[i] = softplus(u[i][i] + b2)
    if (jt == it && tj == ti) {
        #pragma unroll
        for (int r = 0; r < 4; ++r)
            g_T0[i0 + ti + 16 * r] = softplusf(f2hsum(acc[r][r]) + b2v);
    }

    __syncthreads();
    #pragma unroll
    for (int r = 0; r < 4; ++r) {
        float e = 0.f;
        #pragma unroll
        for (int cc = 0; cc < 4; ++cc)
            e += expf(f2hsum(acc[r][cc]) + b2v);
        rowred[ti + 16 * r][tj] = e;
    }
    __syncthreads();
    if (t < 64) {
        float s = 0.f;
        #pragma unroll
        for (int cc = 0; cc < 16; ++cc) s += rowred[t][cc];
        g_rowpartT[(i0 + t) * NJT + jt] = s;
    }

    // ---- last-block fused final reduction ----
    __threadfence();
    __syncthreads();
    if (t == 0) {
        unsigned old = atomicAdd(&g_done, 1u);
        sLast = (old == 255u);
    }
    __syncthreads();
    if (!sLast) return;
    __threadfence();   // acquire: make all blocks' writes visible

    double kl = 0.0, t0 = 0.0, L = 0.0;
    #pragma unroll
    for (int q = 0; q < 4; ++q) {
        int i = t + q * 256;
        const float4* rp = (const float4*)&g_rowpartT[i * NJT];
        float4 v0 = rp[0], v1 = rp[1], v2 = rp[2], v3 = rp[3];
        float rs = ((v0.x + v0.y) + (v0.z + v0.w))
                 + ((v1.x + v1.y) + (v1.z + v1.w))
                 + ((v2.x + v2.y) + (v2.z + v2.w))
                 + ((v3.x + v3.y) + (v3.z + v3.w));
        kl += (double)g_klpart[i];
        t0 += (double)g_T0[i];
        // logsumexp_j softplus(u) = log(B + sum_j e^u)
        L  += (double)logf((float)B_SZ + rs);
    }
    #pragma unroll
    for (int off = 16; off > 0; off >>= 1) {
        kl += __shfl_xor_sync(0xFFFFFFFFu, kl, off);
        t0 += __shfl_xor_sync(0xFFFFFFFFu, t0, off);
        L  += __shfl_xor_sync(0xFFFFFFFFu, L,  off);
    }
    if ((t & 31) == 0) {
        sred[0][t >> 5] = kl; sred[1][t >> 5] = t0; sred[2][t >> 5] = L;
    }
    __syncthreads();
    if (t == 0) {
        double a = 0, b = 0, c = 0;
        #pragma unroll
        for (int i = 0; i < 8; ++i) {
            a += sred[0][i]; b += sred[1][i]; c += sred[2][i];
        }
        double d_skl = a / (double)B_SZ * 0.5;
        double t0m   = b / (double)B_SZ;
        double meanL = c / (double)B_SZ;
        double lower = t0m - (meanL - log((double)B_SZ));
        out[0] = (float)(d_skl - lower);
        g_done = 0u;   // self-restore for next graph replay
    }
}

// ---------------------------------------------------------------------------
extern "C" void kernel_launch(void* const* d_in, const int* in_sizes, int n_in,
                              void* d_out, int out_size)
{
    const float* zl    = (const float*)d_in[0];
    const float* zv    = (const float*)d_in[1];
    const float* fclw  = (const float*)d_in[2];
    const float* fclb  = (const float*)d_in[3];
    const float* fcvw  = (const float*)d_in[4];
    const float* fcvb  = (const float*)d_in[5];
    const float* W1    = (const float*)d_in[6];
    const float* b1    = (const float*)d_in[7];
    const float* W2    = (const float*)d_in[8];
    const float* b2    = (const float*)d_in[9];
    const float* eps1  = (const float*)d_in[10];
    const float* eps2  = (const float*)d_in[11];
    float* out = (float*)d_out;

    k1_fuse<<<B_SZ, 192>>>(zl, zv, fclw, fclb, fcvw, fcvb, eps1, eps2);
    k2_gemm<<<dim3(16, 5, 2), 256>>>(W1, b1);
    k3_pair<<<dim3(16, 16), 256>>>(W2, b2, out);
}

// round 8
// speedup vs baseline: 1.0366x; 1.0037x over previous
#include <cuda_runtime.h>
#include <math.h>

#define B_SZ   1024
#define HID    384
#define MH     300
#define OPAD   320   // padded row stride; cols 300..319 stay zero (zero-init globals)
#define NJT    16    // j-tiles in k3
#define NTILE  256   // total k3 tiles
#define NCTA3  296   // persistent CTAs for k3 (2 per SM)

typedef unsigned long long u64;

// Scratch (device globals; allocations forbidden). Zero-initialized at load;
// padding columns are never written, so they remain exactly 0.0f.
__device__ float g_s1[B_SZ * HID];
__device__ float g_s2[B_SZ * HID];
__device__ float g_Axb[B_SZ * OPAD];
__device__ float g_By [B_SZ * OPAD];
__device__ float g_klpart[B_SZ];
__device__ float g_T0[B_SZ];
__device__ float g_rowpartT[B_SZ * NJT];   // [i][jt]
__device__ unsigned g_tile;                // work-stealing counter; self-reset
__device__ unsigned g_done;                // arrival counter; self-reset

__device__ __forceinline__ float softplusf(float x) {
    return fmaxf(x, 0.f) + log1pf(expf(-fabsf(x)));
}

// Packed f32x2 ops on u64-resident data
__device__ __forceinline__ u64 f2add_u(u64 a, u64 b) {
    u64 d; asm("add.rn.f32x2 %0, %1, %2;" : "=l"(d) : "l"(a), "l"(b)); return d;
}
__device__ __forceinline__ u64 f2fma_u(u64 a, u64 b, u64 c) {
    u64 d; asm("fma.rn.f32x2 %0, %1, %2, %3;" : "=l"(d) : "l"(a), "l"(b), "l"(c)); return d;
}
__device__ __forceinline__ u64 f2relu_u(u64 a) {
    float lo, hi;
    asm("mov.b64 {%0,%1}, %2;" : "=f"(lo), "=f"(hi) : "l"(a));
    lo = fmaxf(lo, 0.f);
    hi = fmaxf(hi, 0.f);
    u64 d;
    asm("mov.b64 %0, {%1,%2};" : "=l"(d) : "f"(lo), "f"(hi));
    return d;
}
__device__ __forceinline__ float f2hsum(u64 a) {
    float lo, hi;
    asm("mov.b64 {%0,%1}, %2;" : "=f"(lo), "=f"(hi) : "l"(a));
    return lo + hi;
}
__device__ __forceinline__ u64 fpack(float x, float y) {
    u64 d; asm("mov.b64 %0, {%1,%2};" : "=l"(d) : "f"(x), "f"(y)); return d;
}

// ---------------------------------------------------------------------------
// K1: per-batch-row fused  einsum -> (mu,sig) -> sample -> KL partial
// grid 1024, block 192. HBM-bound (176 MB).  Streaming loads (.cs).
// ---------------------------------------------------------------------------
__global__ __launch_bounds__(192) void k1_fuse(
    const float* __restrict__ zl, const float* __restrict__ zv,
    const float* __restrict__ wl_g, const float* __restrict__ bl_g,
    const float* __restrict__ wv_g, const float* __restrict__ bv_g,
    const float* __restrict__ eps1, const float* __restrict__ eps2)
{
    __shared__ float z1s[768], z2s[768];
    __shared__ float wls[20], wvs[36];
    __shared__ float redw[6];
    const int b = blockIdx.x, t = threadIdx.x;
    if (t < 20) wls[t] = wl_g[t];
    if (t >= 32 && t < 68) wvs[t - 32] = wv_g[t - 32];
    __syncthreads();
    const float bl = bl_g[0], bv = bv_g[0];
    {
        const float4* p = (const float4*)(zl + (size_t)b * 20 * 768) + t;
        float4 a = make_float4(bl, bl, bl, bl);
        #pragma unroll
        for (int s = 0; s < 20; ++s) {
            float4 v = __ldcs(p + s * 192);
            float w = wls[s];
            a.x = fmaf(v.x, w, a.x); a.y = fmaf(v.y, w, a.y);
            a.z = fmaf(v.z, w, a.z); a.w = fmaf(v.w, w, a.w);
        }
        ((float4*)z1s)[t] = a;
    }
    {
        const float4* p = (const float4*)(zv + (size_t)b * 36 * 768) + t;
        float4 a = make_float4(bv, bv, bv, bv);
        #pragma unroll
        for (int s = 0; s < 36; ++s) {
            float4 v = __ldcs(p + s * 192);
            float w = wvs[s];
            a.x = fmaf(v.x, w, a.x); a.y = fmaf(v.y, w, a.y);
            a.z = fmaf(v.z, w, a.z); a.w = fmaf(v.w, w, a.w);
        }
        ((float4*)z2s)[t] = a;
    }
    __syncthreads();
    float klacc = 0.f;
    #pragma unroll
    for (int q = 0; q < 2; ++q) {
        int k = t + q * 192;
        float mu1 = z1s[k], mu2 = z2s[k];
        float sg1 = softplusf(z1s[k + HID]) + 1e-7f;
        float sg2 = softplusf(z2s[k + HID]) + 1e-7f;
        float e1 = eps1[b * HID + k], e2 = eps2[b * HID + k];
        float s1v = fmaf(sg1, e1, mu1);
        float s2v = fmaf(sg2, e2, mu2);
        g_s1[b * HID + k] = s1v;
        g_s2[b * HID + k] = s2v;
        float d1 = (s1v - mu2) / sg2;
        float d2 = (s2v - mu1) / sg1;
        klacc += 0.5f * (d1 * d1 + d2 * d2 - e1 * e1 - e2 * e2);
    }
    #pragma unroll
    for (int off = 16; off > 0; off >>= 1)
        klacc += __shfl_xor_sync(0xFFFFFFFFu, klacc, off);
    if ((t & 31) == 0) redw[t >> 5] = klacc;
    __syncthreads();
    if (t == 0)
        g_klpart[b] = redw[0] + redw[1] + redw[2] + redw[3] + redw[4] + redw[5];
}

// ---------------------------------------------------------------------------
// K2: Axb = s1 @ W1x^T + b1 ;  By = s2 @ W1y^T
// grid (16,5,2), block 256.  Tile 64x64, u64-packed over k, 4x4/thread.
// ---------------------------------------------------------------------------
__global__ __launch_bounds__(256) void k2_gemm(
    const float* __restrict__ W1, const float* __restrict__ b1)
{
    __shared__ u64 As[64][17];
    __shared__ u64 Ws[64][17];

    const int z  = blockIdx.z;
    const int r0 = blockIdx.x * 64;
    const int c0 = blockIdx.y * 64;
    const float* S = z ? g_s2 : g_s1;
    float*       O = z ? g_By : g_Axb;
    const int koff = z ? HID : 0;

    const int t  = threadIdx.x;
    const int tj = t & 15;
    const int ti = t >> 4;

    u64 acc[4][4];
    #pragma unroll
    for (int r = 0; r < 4; ++r)
        #pragma unroll
        for (int c = 0; c < 4; ++c) acc[r][c] = 0ull;

    for (int kk2 = 0; kk2 < 192; kk2 += 16) {
        __syncthreads();
        #pragma unroll
        for (int i = 0; i < 4; ++i) {
            int e = t + i * 256;
            int row = e >> 4, k2 = e & 15;
            As[row][k2] = *(const u64*)&S[(r0 + row) * HID + (kk2 + k2) * 2];
            int col = c0 + row;
            Ws[row][k2] = (col < MH)
                ? *(const u64*)&W1[col * 768 + koff + (kk2 + k2) * 2] : 0ull;
        }
        __syncthreads();
        #pragma unroll 4
        for (int k2 = 0; k2 < 16; ++k2) {
            u64 a[4], w[4];
            #pragma unroll
            for (int r = 0; r < 4; ++r) a[r] = As[ti + 16 * r][k2];
            #pragma unroll
            for (int c = 0; c < 4; ++c) w[c] = Ws[tj + 16 * c][k2];
            #pragma unroll
            for (int r = 0; r < 4; ++r)
                #pragma unroll
                for (int c = 0; c < 4; ++c)
                    acc[r][c] = f2fma_u(a[r], w[c], acc[r][c]);
        }
    }
    #pragma unroll
    for (int r = 0; r < 4; ++r) {
        int row = r0 + ti + 16 * r;
        #pragma unroll
        for (int c = 0; c < 4; ++c) {
            int col = c0 + tj + 16 * c;
            if (col < MH) {
                float v = f2hsum(acc[r][c]);
                if (z == 0) v += b1[col];
                O[row * OPAD + col] = v;
            }
        }
    }
}

// ---------------------------------------------------------------------------
// K3: persistent work-stealing pairwise grid + fused final reduction.
// u[i][j] = sum_k relu(Axb[j,k] + By[i,k]) * w2[k]
// grid NCTA3=296, block 256. 64x64 tiles pulled from g_tile counter.
// 4x4 pairs/thread, u64-packed, register-prefetch pipeline.
// Diagonal blocks write T0.  CTA arriving last (g_done) reduces everything.
// ---------------------------------------------------------------------------
__global__ __launch_bounds__(256) void k3_pair(
    const float* __restrict__ W2, const float* __restrict__ b2g,
    float* __restrict__ out)
{
    __shared__ u64 Bys[64][17];
    __shared__ u64 Axs[64][17];
    __shared__ u64 w2s[160];
    __shared__ float rowred[64][17];
    __shared__ unsigned sTile;
    __shared__ int sLast;
    __shared__ double sred[3][8];

    const int t  = threadIdx.x;
    const int tj = t & 15;
    const int ti = t >> 4;

    if (t < 160) {
        int k = 2 * t;
        float2 w = make_float2(k < MH ? W2[k] : 0.f,
                               k + 1 < MH ? W2[k + 1] : 0.f);
        w2s[t] = *(const u64*)&w;
    }
    const float b2v = b2g[0];

    const int rA = t >> 3,          fA = t & 7;
    const int rB = (t + 256) >> 3,  fB = t & 7;

    for (;;) {
        __syncthreads();   // protect rowred/smem from previous tile; align for sTile
        if (t == 0) sTile = atomicAdd(&g_tile, 1u);
        __syncthreads();
        const unsigned tile = sTile;
        if (tile >= NTILE) break;
        const int jt = tile & 15, it = tile >> 4;
        const int i0 = it * 64, j0 = jt * 64;

        const float* byA = &g_By [(i0 + rA) * OPAD + fA * 4];
        const float* byB = &g_By [(i0 + rB) * OPAD + fB * 4];
        const float* axA = &g_Axb[(j0 + rA) * OPAD + fA * 4];
        const float* axB = &g_Axb[(j0 + rB) * OPAD + fB * 4];

        u64 acc[4][4];
        #pragma unroll
        for (int r = 0; r < 4; ++r)
            #pragma unroll
            for (int c = 0; c < 4; ++c) acc[r][c] = 0ull;

        float4 pb0 = *(const float4*)(byA);
        float4 pb1 = *(const float4*)(byB);
        float4 pa0 = *(const float4*)(axA);
        float4 pa1 = *(const float4*)(axB);

        for (int c = 0; c < 10; ++c) {
            __syncthreads();
            Bys[rA][2 * fA]     = fpack(pb0.x, pb0.y);
            Bys[rA][2 * fA + 1] = fpack(pb0.z, pb0.w);
            Bys[rB][2 * fB]     = fpack(pb1.x, pb1.y);
            Bys[rB][2 * fB + 1] = fpack(pb1.z, pb1.w);
            Axs[rA][2 * fA]     = fpack(pa0.x, pa0.y);
            Axs[rA][2 * fA + 1] = fpack(pa0.z, pa0.w);
            Axs[rB][2 * fB]     = fpack(pa1.x, pa1.y);
            Axs[rB][2 * fB + 1] = fpack(pa1.z, pa1.w);
            __syncthreads();
            if (c < 9) {
                int off = (c + 1) * 32;
                pb0 = *(const float4*)(byA + off);
                pb1 = *(const float4*)(byB + off);
                pa0 = *(const float4*)(axA + off);
                pa1 = *(const float4*)(axB + off);
            }
            #pragma unroll 4
            for (int k2 = 0; k2 < 16; ++k2) {
                u64 wp = w2s[c * 16 + k2];
                u64 a[4], b[4];
                #pragma unroll
                for (int cc = 0; cc < 4; ++cc) a[cc] = Axs[tj + 16 * cc][k2];
                #pragma unroll
                for (int r = 0; r < 4; ++r) b[r] = Bys[ti + 16 * r][k2];
                #pragma unroll
                for (int r = 0; r < 4; ++r)
                    #pragma unroll
                    for (int cc = 0; cc < 4; ++cc)
                        acc[r][cc] = f2fma_u(f2relu_u(f2add_u(a[cc], b[r])),
                                             wp, acc[r][cc]);
            }
        }

        // Diagonal blocks: T0[i] = softplus(u[i][i] + b2)
        if (jt == it && tj == ti) {
            #pragma unroll
            for (int r = 0; r < 4; ++r)
                g_T0[i0 + ti + 16 * r] = softplusf(f2hsum(acc[r][r]) + b2v);
        }

        __syncthreads();
        #pragma unroll
        for (int r = 0; r < 4; ++r) {
            float e = 0.f;
            #pragma unroll
            for (int cc = 0; cc < 4; ++cc)
                e += expf(f2hsum(acc[r][cc]) + b2v);
            rowred[ti + 16 * r][tj] = e;
        }
        __syncthreads();
        if (t < 64) {
            float s = 0.f;
            #pragma unroll
            for (int cc = 0; cc < 16; ++cc) s += rowred[t][cc];
            g_rowpartT[(i0 + t) * NJT + jt] = s;
        }
    }

    // ---- last-arriving CTA does the final reduction ----
    __threadfence();
    __syncthreads();
    if (t == 0) {
        unsigned old = atomicAdd(&g_done, 1u);
        sLast = (old == NCTA3 - 1u);
    }
    __syncthreads();
    if (!sLast) return;
    __threadfence();   // acquire: all CTAs' writes visible

    double kl = 0.0, t0 = 0.0, L = 0.0;
    #pragma unroll
    for (int q = 0; q < 4; ++q) {
        int i = t + q * 256;
        const float4* rp = (const float4*)&g_rowpartT[i * NJT];
        float4 v0 = rp[0], v1 = rp[1], v2 = rp[2], v3 = rp[3];
        float rs = ((v0.x + v0.y) + (v0.z + v0.w))
                 + ((v1.x + v1.y) + (v1.z + v1.w))
                 + ((v2.x + v2.y) + (v2.z + v2.w))
                 + ((v3.x + v3.y) + (v3.z + v3.w));
        kl += (double)g_klpart[i];
        t0 += (double)g_T0[i];
        // logsumexp_j softplus(u) = log(B + sum_j e^u)
        L  += (double)logf((float)B_SZ + rs);
    }
    #pragma unroll
    for (int off = 16; off > 0; off >>= 1) {
        kl += __shfl_xor_sync(0xFFFFFFFFu, kl, off);
        t0 += __shfl_xor_sync(0xFFFFFFFFu, t0, off);
        L  += __shfl_xor_sync(0xFFFFFFFFu, L,  off);
    }
    if ((t & 31) == 0) {
        sred[0][t >> 5] = kl; sred[1][t >> 5] = t0; sred[2][t >> 5] = L;
    }
    __syncthreads();
    if (t == 0) {
        double a = 0, b = 0, c = 0;
        #pragma unroll
        for (int i = 0; i < 8; ++i) {
            a += sred[0][i]; b += sred[1][i]; c += sred[2][i];
        }
        double d_skl = a / (double)B_SZ * 0.5;
        double t0m   = b / (double)B_SZ;
        double meanL = c / (double)B_SZ;
        double lower = t0m - (meanL - log((double)B_SZ));
        out[0] = (float)(d_skl - lower);
        g_done = 0u;   // self-restore for next graph replay
        g_tile = 0u;
    }
}

// ---------------------------------------------------------------------------
extern "C" void kernel_launch(void* const* d_in, const int* in_sizes, int n_in,
                              void* d_out, int out_size)
{
    const float* zl    = (const float*)d_in[0];
    const float* zv    = (const float*)d_in[1];
    const float* fclw  = (const float*)d_in[2];
    const float* fclb  = (const float*)d_in[3];
    const float* fcvw  = (const float*)d_in[4];
    const float* fcvb  = (const float*)d_in[5];
    const float* W1    = (const float*)d_in[6];
    const float* b1    = (const float*)d_in[7];
    const float* W2    = (const float*)d_in[8];
    const float* b2    = (const float*)d_in[9];
    const float* eps1  = (const float*)d_in[10];
    const float* eps2  = (const float*)d_in[11];
    float* out = (float*)d_out;

    k1_fuse<<<B_SZ, 192>>>(zl, zv, fclw, fclb, fcvw, fcvb, eps1, eps2);
    k2_gemm<<<dim3(16, 5, 2), 256>>>(W1, b1);
    k3_pair<<<NCTA3, 256>>>(W2, b2, out);
}